// round 2
// baseline (speedup 1.0000x reference)
#include <cuda_runtime.h>
#include <cstdint>

// ---------------------------------------------------------------------------
// VQ-VAE VectorQuantizer, GB300 sm_103a — bit-exact emulation of the fp32
// reference semantics (CPU XLA hypothesis):
//   zz   = sequential fp32 mul+add over c (ascending)
//   e2_k = sequential fp32 mul+add over c (ascending)
//   dot_k= sequential fp32 FMA chain over c (ascending)  [Eigen gebp order]
//   d_k  = fl(fl(zz + e2_k) - fl(2*dot_k)); argmin first-min, k ascending
//   q    = fl(z + fl(e - z))   (straight-through estimator, per-element fp32)
//
// The per-lane chain order is preserved while vectorizing ACROSS codes with
// fma.rn.f32x2: lane0/lane1 = two codes, each lane its own exact chain.
// Codebook is transposed into smem (e_T[c][k]) so one broadcast LDS.128
// feeds 4 codes at channel c.
// ---------------------------------------------------------------------------

constexpr int CC     = 64;          // channels
constexpr int CHW    = 4096;        // H*W
constexpr int NPIX   = 65536;       // B*H*W
constexpr int KCB    = 1024;        // codebook entries
constexpr int CHUNK  = 128;         // codes per smem chunk
constexpr int NCHUNK = KCB / CHUNK; // 8
constexpr int NTHR   = 256;
constexpr int NBLK   = NPIX / NTHR; // 256
constexpr int RS     = 132;         // e_T row stride in floats (pad vs 128)

constexpr int Q_ELEMS = 4194304;
constexpr int LOSS0   = Q_ELEMS;
constexpr int LOSS1   = Q_ELEMS + 1;
constexpr int IDX0    = Q_ELEMS + 2;

__device__ float g_e2[KCB];
__device__ float g_part[NBLK];

// ---- packed f32x2 helpers --------------------------------------------------
__device__ __forceinline__ unsigned long long pack2f(float lo, float hi) {
    unsigned long long r;
    asm("mov.b64 %0, {%1, %2};" : "=l"(r) : "f"(lo), "f"(hi));
    return r;
}
__device__ __forceinline__ void unpack2f(unsigned long long v, float& lo, float& hi) {
    asm("mov.b64 {%0, %1}, %2;" : "=f"(lo), "=f"(hi) : "l"(v));
}
__device__ __forceinline__ unsigned long long ffma2(unsigned long long a,
                                                    unsigned long long b,
                                                    unsigned long long c) {
    unsigned long long d;
    asm("fma.rn.f32x2 %0, %1, %2, %3;" : "=l"(d) : "l"(a), "l"(b), "l"(c));
    return d;
}

// ---- init: ||e_k||^2 with reference's sequential mul+add order -------------
__global__ void vq_init(const float* __restrict__ emb) {
    int k = blockIdx.x * blockDim.x + threadIdx.x;
    if (k < KCB) {
        const float* r = emb + k * CC;
        float s = 0.f;
        #pragma unroll
        for (int c = 0; c < CC; c++)
            s = __fadd_rn(s, __fmul_rn(r[c], r[c]));
        g_e2[k] = s;
    }
}

// ---- main ------------------------------------------------------------------
__global__ __launch_bounds__(NTHR, 2)
void vq_main(const float* __restrict__ z, const float* __restrict__ emb,
             float* __restrict__ out) {
    __shared__ __align__(16) float eT[CC * RS];   // transposed chunk [c][k]
    __shared__ float e2s[CHUNK];
    __shared__ float reds[NTHR / 32];

    const int p  = blockIdx.x * NTHR + threadIdx.x;
    const int b  = p >> 12;
    const int hw = p & 4095;
    const float* zp = z + (size_t)b * (CC * CHW) + hw;

    // z vector in registers (fully unrolled constant indices)
    float zr[CC];
    #pragma unroll
    for (int c = 0; c < CC; c++) zr[c] = zp[c * CHW];

    // ||z||^2: exact reference order (sequential mul + add, c ascending)
    float zz = 0.f;
    #pragma unroll
    for (int c = 0; c < CC; c++)
        zz = __fadd_rn(zz, __fmul_rn(zr[c], zr[c]));

    float best  = 3.4e38f;
    int   bestk = 0;

    for (int ch = 0; ch < NCHUNK; ch++) {
        if (ch) __syncthreads();   // previous chunk fully consumed
        // ---- load + transpose chunk: 4x4 tiles, STS.128 into e_T[c][k] ----
        const float* ebase = emb + ch * CHUNK * CC;
        #pragma unroll
        for (int it = 0; it < 2; it++) {
            int idx = threadIdx.x + it * NTHR;   // 0..511
            int k0  = (idx & 31) * 4;            // code quad
            int c0  = (idx >> 5) * 4;            // channel quad
            float4 r0 = *reinterpret_cast<const float4*>(ebase + (k0 + 0) * CC + c0);
            float4 r1 = *reinterpret_cast<const float4*>(ebase + (k0 + 1) * CC + c0);
            float4 r2 = *reinterpret_cast<const float4*>(ebase + (k0 + 2) * CC + c0);
            float4 r3 = *reinterpret_cast<const float4*>(ebase + (k0 + 3) * CC + c0);
            *reinterpret_cast<float4*>(eT + (c0 + 0) * RS + k0) = make_float4(r0.x, r1.x, r2.x, r3.x);
            *reinterpret_cast<float4*>(eT + (c0 + 1) * RS + k0) = make_float4(r0.y, r1.y, r2.y, r3.y);
            *reinterpret_cast<float4*>(eT + (c0 + 2) * RS + k0) = make_float4(r0.z, r1.z, r2.z, r3.z);
            *reinterpret_cast<float4*>(eT + (c0 + 3) * RS + k0) = make_float4(r0.w, r1.w, r2.w, r3.w);
        }
        if (threadIdx.x < CHUNK) e2s[threadIdx.x] = g_e2[ch * CHUNK + threadIdx.x];
        __syncthreads();

        // ---- 16 groups of 8 codes: 4 f32x2 chains, lane order = c ascending
        for (int kg = 0; kg < CHUNK / 8; kg++) {
            unsigned long long a0 = 0ull, a1 = 0ull, a2 = 0ull, a3 = 0ull;
            #pragma unroll
            for (int c = 0; c < CC; c++) {
                unsigned long long zd = pack2f(zr[c], zr[c]);
                const ulonglong2* q =
                    reinterpret_cast<const ulonglong2*>(eT + c * RS + kg * 8);
                ulonglong2 v0 = q[0];   // codes k..k+3 (broadcast LDS.128)
                ulonglong2 v1 = q[1];   // codes k+4..k+7
                a0 = ffma2(zd, v0.x, a0);
                a1 = ffma2(zd, v0.y, a1);
                a2 = ffma2(zd, v1.x, a2);
                a3 = ffma2(zd, v1.y, a3);
            }
            float dt[8];
            unpack2f(a0, dt[0], dt[1]);
            unpack2f(a1, dt[2], dt[3]);
            unpack2f(a2, dt[4], dt[5]);
            unpack2f(a3, dt[6], dt[7]);
            int kb = ch * CHUNK + kg * 8;
            #pragma unroll
            for (int j = 0; j < 8; j++) {
                // d = fl(fl(zz + e2) - fl(2*dot)) — reference op order
                float t = __fadd_rn(zz, e2s[kg * 8 + j]);
                float d = __fsub_rn(t, __fmul_rn(2.0f, dt[j]));
                if (d < best) { best = d; bestk = kb + j; }   // first-min ties
            }
        }
    }

    // ---- epilogue: gather winner, STE-exact q, loss partial ---------------
    float sumsq = 0.f;
    const float4* erow = reinterpret_cast<const float4*>(emb + (size_t)bestk * CC);
    float* qout = out + (size_t)b * (CC * CHW) + hw;
    #pragma unroll
    for (int i = 0; i < CC / 4; i++) {
        float4 e4 = __ldg(erow + i);
        float ev[4] = {e4.x, e4.y, e4.z, e4.w};
        #pragma unroll
        for (int j = 0; j < 4; j++) {
            int c = 4 * i + j;
            float dd = __fsub_rn(ev[j], zr[c]);          // fl(e - z)
            sumsq = __fadd_rn(sumsq, __fmul_rn(dd, dd));
            qout[c * CHW] = __fadd_rn(zr[c], dd);        // fl(z + fl(e - z))
        }
    }
    out[IDX0 + p] = (float)bestk;

    // deterministic block reduction -> per-block partial
    #pragma unroll
    for (int o = 16; o; o >>= 1)
        sumsq += __shfl_xor_sync(0xffffffffu, sumsq, o);
    if ((threadIdx.x & 31) == 0) reds[threadIdx.x >> 5] = sumsq;
    __syncthreads();
    if (threadIdx.x == 0) {
        float s = 0.f;
        #pragma unroll
        for (int w = 0; w < NTHR / 32; w++) s += reds[w];
        g_part[blockIdx.x] = s;
    }
}

// ---- finalize: deterministic loss sum --------------------------------------
__global__ void vq_fin(float* __restrict__ out) {
    float s = 0.f;
    for (int i = 0; i < NBLK; i++) s += g_part[i];
    float loss = s * (1.0f / (float)Q_ELEMS);
    out[LOSS0] = loss;
    out[LOSS1] = loss;
}

extern "C" void kernel_launch(void* const* d_in, const int* in_sizes, int n_in,
                              void* d_out, int out_size) {
    const float* z   = (const float*)d_in[0];
    const float* emb = (const float*)d_in[1];
    float* out = (float*)d_out;

    vq_init<<<(KCB + NTHR - 1) / NTHR, NTHR>>>(emb);
    vq_main<<<NBLK, NTHR>>>(z, emb, out);
    vq_fin<<<1, 1>>>(out);
}

// round 3
// speedup vs baseline: 1.4044x; 1.4044x over previous
#include <cuda_runtime.h>
#include <cstdint>

// ---------------------------------------------------------------------------
// VQ-VAE VectorQuantizer, GB300 sm_103a — bit-exact fp32 reference emulation.
// R3: 2 pixels per thread so each broadcast LDS.128 feeds 4 FFMA2 (was 2),
// halving LDS-pipe pressure (R2 was LDS-issue-bound at ~300us).
//   zz   = sequential fp32 mul+add over c (ascending)
//   e2_k = sequential fp32 mul+add over c (ascending)
//   dot_k= sequential fp32 FMA chain over c (ascending)
//   d_k  = fl(fl(zz + e2_k) - fl(2*dot_k)); argmin first-min, k ascending
//   q    = fl(z + fl(e - z))
// ---------------------------------------------------------------------------

constexpr int CC     = 64;           // channels
constexpr int CHW    = 4096;         // H*W
constexpr int NPIX   = 65536;        // B*H*W
constexpr int KCB    = 1024;         // codebook entries
constexpr int CHUNK  = 128;          // codes per smem chunk
constexpr int NCHUNK = KCB / CHUNK;  // 8
constexpr int NTHR   = 256;
constexpr int PZ     = 2;            // pixels per thread
constexpr int PIXBLK = NTHR * PZ;    // 512 pixels per block
constexpr int NBLK   = NPIX / PIXBLK;// 128
constexpr int RS     = 132;          // e_T row stride in floats (pad)

constexpr int Q_ELEMS = 4194304;
constexpr int LOSS0   = Q_ELEMS;
constexpr int LOSS1   = Q_ELEMS + 1;
constexpr int IDX0    = Q_ELEMS + 2;

__device__ float g_e2[KCB];
__device__ float g_part[NBLK];

// ---- packed f32x2 helpers --------------------------------------------------
__device__ __forceinline__ unsigned long long pack2f(float lo, float hi) {
    unsigned long long r;
    asm("mov.b64 %0, {%1, %2};" : "=l"(r) : "f"(lo), "f"(hi));
    return r;
}
__device__ __forceinline__ void unpack2f(unsigned long long v, float& lo, float& hi) {
    asm("mov.b64 {%0, %1}, %2;" : "=f"(lo), "=f"(hi) : "l"(v));
}
__device__ __forceinline__ unsigned long long ffma2(unsigned long long a,
                                                    unsigned long long b,
                                                    unsigned long long c) {
    unsigned long long d;
    asm("fma.rn.f32x2 %0, %1, %2, %3;" : "=l"(d) : "l"(a), "l"(b), "l"(c));
    return d;
}

// ---- init: ||e_k||^2 with reference's sequential mul+add order -------------
__global__ void vq_init(const float* __restrict__ emb) {
    int k = blockIdx.x * blockDim.x + threadIdx.x;
    if (k < KCB) {
        const float* r = emb + k * CC;
        float s = 0.f;
        #pragma unroll
        for (int c = 0; c < CC; c++)
            s = __fadd_rn(s, __fmul_rn(r[c], r[c]));
        g_e2[k] = s;
    }
}

// ---- main ------------------------------------------------------------------
__global__ __launch_bounds__(NTHR)
void vq_main(const float* __restrict__ z, const float* __restrict__ emb,
             float* __restrict__ out) {
    __shared__ __align__(16) float eT[CC * RS];   // transposed chunk [c][k]
    __shared__ float e2s[CHUNK];
    __shared__ float reds[NTHR / 32];

    // two pixels per thread: p0 = base + tid, p1 = p0 + NTHR
    const int p0  = blockIdx.x * PIXBLK + threadIdx.x;
    const int p1  = p0 + NTHR;
    const int b0  = p0 >> 12, hw0 = p0 & 4095;
    const int b1  = p1 >> 12, hw1 = p1 & 4095;
    const float* zp0 = z + (size_t)b0 * (CC * CHW) + hw0;
    const float* zp1 = z + (size_t)b1 * (CC * CHW) + hw1;

    float zr0[CC], zr1[CC];
    #pragma unroll
    for (int c = 0; c < CC; c++) zr0[c] = zp0[c * CHW];
    #pragma unroll
    for (int c = 0; c < CC; c++) zr1[c] = zp1[c * CHW];

    // ||z||^2 in exact reference order
    float zz0 = 0.f, zz1 = 0.f;
    #pragma unroll
    for (int c = 0; c < CC; c++) zz0 = __fadd_rn(zz0, __fmul_rn(zr0[c], zr0[c]));
    #pragma unroll
    for (int c = 0; c < CC; c++) zz1 = __fadd_rn(zz1, __fmul_rn(zr1[c], zr1[c]));

    float best0 = 3.4e38f, best1 = 3.4e38f;
    int   bk0 = 0, bk1 = 0;

    for (int ch = 0; ch < NCHUNK; ch++) {
        if (ch) __syncthreads();
        // ---- load + transpose chunk into eT[c][k] -------------------------
        const float* ebase = emb + ch * CHUNK * CC;
        #pragma unroll
        for (int it = 0; it < 2; it++) {
            int idx = threadIdx.x + it * NTHR;   // 0..511
            int k0  = (idx & 31) * 4;
            int c0  = (idx >> 5) * 4;
            float4 r0 = *reinterpret_cast<const float4*>(ebase + (k0 + 0) * CC + c0);
            float4 r1 = *reinterpret_cast<const float4*>(ebase + (k0 + 1) * CC + c0);
            float4 r2 = *reinterpret_cast<const float4*>(ebase + (k0 + 2) * CC + c0);
            float4 r3 = *reinterpret_cast<const float4*>(ebase + (k0 + 3) * CC + c0);
            *reinterpret_cast<float4*>(eT + (c0 + 0) * RS + k0) = make_float4(r0.x, r1.x, r2.x, r3.x);
            *reinterpret_cast<float4*>(eT + (c0 + 1) * RS + k0) = make_float4(r0.y, r1.y, r2.y, r3.y);
            *reinterpret_cast<float4*>(eT + (c0 + 2) * RS + k0) = make_float4(r0.z, r1.z, r2.z, r3.z);
            *reinterpret_cast<float4*>(eT + (c0 + 3) * RS + k0) = make_float4(r0.w, r1.w, r2.w, r3.w);
        }
        if (threadIdx.x < CHUNK) e2s[threadIdx.x] = g_e2[ch * CHUNK + threadIdx.x];
        __syncthreads();

        // ---- 16 groups of 8 codes; 4 f32x2 chains per pixel ---------------
        #pragma unroll 1
        for (int kg = 0; kg < CHUNK / 8; kg++) {
            unsigned long long a00 = 0ull, a01 = 0ull, a02 = 0ull, a03 = 0ull;
            unsigned long long a10 = 0ull, a11 = 0ull, a12 = 0ull, a13 = 0ull;
            const char* rowp = reinterpret_cast<const char*>(eT + kg * 8);
            #pragma unroll
            for (int c = 0; c < CC; c++) {
                const ulonglong2* q =
                    reinterpret_cast<const ulonglong2*>(rowp + c * (RS * 4));
                ulonglong2 v0 = q[0];   // codes k..k+3   (broadcast LDS.128)
                ulonglong2 v1 = q[1];   // codes k+4..k+7
                unsigned long long zd0 = pack2f(zr0[c], zr0[c]);
                unsigned long long zd1 = pack2f(zr1[c], zr1[c]);
                a00 = ffma2(zd0, v0.x, a00);
                a01 = ffma2(zd0, v0.y, a01);
                a02 = ffma2(zd0, v1.x, a02);
                a03 = ffma2(zd0, v1.y, a03);
                a10 = ffma2(zd1, v0.x, a10);
                a11 = ffma2(zd1, v0.y, a11);
                a12 = ffma2(zd1, v1.x, a12);
                a13 = ffma2(zd1, v1.y, a13);
            }
            float d0[8], d1[8];
            unpack2f(a00, d0[0], d0[1]); unpack2f(a01, d0[2], d0[3]);
            unpack2f(a02, d0[4], d0[5]); unpack2f(a03, d0[6], d0[7]);
            unpack2f(a10, d1[0], d1[1]); unpack2f(a11, d1[2], d1[3]);
            unpack2f(a12, d1[4], d1[5]); unpack2f(a13, d1[6], d1[7]);
            int kb = ch * CHUNK + kg * 8;
            #pragma unroll
            for (int j = 0; j < 8; j++) {
                float e2 = e2s[kg * 8 + j];
                float s0 = __fsub_rn(__fadd_rn(zz0, e2), __fmul_rn(2.0f, d0[j]));
                float s1 = __fsub_rn(__fadd_rn(zz1, e2), __fmul_rn(2.0f, d1[j]));
                if (s0 < best0) { best0 = s0; bk0 = kb + j; }
                if (s1 < best1) { best1 = s1; bk1 = kb + j; }
            }
        }
    }

    // ---- epilogue: gather winners, STE-exact q, loss partial ---------------
    float sumsq = 0.f;
    {
        const float4* erow = reinterpret_cast<const float4*>(emb + (size_t)bk0 * CC);
        float* qout = out + (size_t)b0 * (CC * CHW) + hw0;
        #pragma unroll
        for (int i = 0; i < CC / 4; i++) {
            float4 e4 = __ldg(erow + i);
            float ev[4] = {e4.x, e4.y, e4.z, e4.w};
            #pragma unroll
            for (int j = 0; j < 4; j++) {
                int c = 4 * i + j;
                float dd = __fsub_rn(ev[j], zr0[c]);
                sumsq = __fadd_rn(sumsq, __fmul_rn(dd, dd));
                qout[c * CHW] = __fadd_rn(zr0[c], dd);
            }
        }
        out[IDX0 + p0] = (float)bk0;
    }
    {
        const float4* erow = reinterpret_cast<const float4*>(emb + (size_t)bk1 * CC);
        float* qout = out + (size_t)b1 * (CC * CHW) + hw1;
        #pragma unroll
        for (int i = 0; i < CC / 4; i++) {
            float4 e4 = __ldg(erow + i);
            float ev[4] = {e4.x, e4.y, e4.z, e4.w};
            #pragma unroll
            for (int j = 0; j < 4; j++) {
                int c = 4 * i + j;
                float dd = __fsub_rn(ev[j], zr1[c]);
                sumsq = __fadd_rn(sumsq, __fmul_rn(dd, dd));
                qout[c * CHW] = __fadd_rn(zr1[c], dd);
            }
        }
        out[IDX0 + p1] = (float)bk1;
    }

    #pragma unroll
    for (int o = 16; o; o >>= 1)
        sumsq += __shfl_xor_sync(0xffffffffu, sumsq, o);
    if ((threadIdx.x & 31) == 0) reds[threadIdx.x >> 5] = sumsq;
    __syncthreads();
    if (threadIdx.x == 0) {
        float s = 0.f;
        #pragma unroll
        for (int w = 0; w < NTHR / 32; w++) s += reds[w];
        g_part[blockIdx.x] = s;
    }
}

// ---- finalize --------------------------------------------------------------
__global__ void vq_fin(float* __restrict__ out) {
    float s = 0.f;
    for (int i = 0; i < NBLK; i++) s += g_part[i];
    float loss = s * (1.0f / (float)Q_ELEMS);
    out[LOSS0] = loss;
    out[LOSS1] = loss;
}

extern "C" void kernel_launch(void* const* d_in, const int* in_sizes, int n_in,
                              void* d_out, int out_size) {
    const float* z   = (const float*)d_in[0];
    const float* emb = (const float*)d_in[1];
    float* out = (float*)d_out;

    vq_init<<<(KCB + NTHR - 1) / NTHR, NTHR>>>(emb);
    vq_main<<<NBLK, NTHR>>>(z, emb, out);
    vq_fin<<<1, 1>>>(out);
}